// round 6
// baseline (speedup 1.0000x reference)
#include <cuda_runtime.h>
#include <cuda_bf16.h>
#include <math.h>
#include <stdint.h>

// ---------------------------------------------------------------------------
// HardNegativeContrastiveLoss N=8192 D=256. Round 6: compute logits ONCE
// (halves the MMA work — mma.sync is issue-rate-capped ~44cyc/HMMA/SMSP),
// store bf16 logits to HBM (134MB, ~30us), then a memory-bound top-k kernel
// scans rows (direct gmem) and columns (SMEM tile transpose) for both
// directions. mma.sync bf16, cp.async double-buffered B panels.
// ---------------------------------------------------------------------------

#define NROWS 8192
#define DIM   256
#define BM    128
#define BN    64
#define NTH   512
#define STR   264               // bf16 elems per SMEM row (528 B, LDSM conflict-free)

// GEMM smem offsets (bytes)
#define SM_A     0
#define SM_B0    67584
#define SM_B1    101376
#define SM_GEMM  135168

__device__ __nv_bfloat16 g_bf[2 * NROWS * DIM];     // [img ; cur] bf16
__device__ __nv_bfloat16 g_logits[(size_t)NROWS * NROWS];  // 134 MB
__device__ float g_partial[128];

// ---- fp32 -> bf16 conversion ----------------------------------------------
__global__ void convert_kernel(const float* __restrict__ a, const float* __restrict__ b) {
    int i = blockIdx.x * blockDim.x + threadIdx.x;
    const int n = NROWS * DIM / 4;
    if (i < n) {
        float4 v = ((const float4*)a)[i];
        __nv_bfloat162* o = (__nv_bfloat162*)(g_bf) + i * 2;
        o[0] = __floats2bfloat162_rn(v.x, v.y);
        o[1] = __floats2bfloat162_rn(v.z, v.w);
    } else if (i < 2 * n) {
        int j = i - n;
        float4 v = ((const float4*)b)[j];
        __nv_bfloat162* o = (__nv_bfloat162*)(g_bf + NROWS * DIM) + j * 2;
        o[0] = __floats2bfloat162_rn(v.x, v.y);
        o[1] = __floats2bfloat162_rn(v.z, v.w);
    }
}

// ---- PTX helpers ----------------------------------------------------------
__device__ __forceinline__ void ldsm4(uint32_t& r0, uint32_t& r1, uint32_t& r2, uint32_t& r3,
                                      uint32_t addr) {
    asm volatile("ldmatrix.sync.aligned.m8n8.x4.shared.b16 {%0,%1,%2,%3}, [%4];"
                 : "=r"(r0), "=r"(r1), "=r"(r2), "=r"(r3) : "r"(addr));
}
__device__ __forceinline__ void mma16816(float* c,
                                         uint32_t a0, uint32_t a1, uint32_t a2, uint32_t a3,
                                         uint32_t b0, uint32_t b1) {
    asm volatile("mma.sync.aligned.m16n8k16.row.col.f32.bf16.bf16.f32 "
                 "{%0,%1,%2,%3}, {%4,%5,%6,%7}, {%8,%9}, {%0,%1,%2,%3};"
                 : "+f"(c[0]), "+f"(c[1]), "+f"(c[2]), "+f"(c[3])
                 : "r"(a0), "r"(a1), "r"(a2), "r"(a3), "r"(b0), "r"(b1));
}
__device__ __forceinline__ void cp_async16(uint32_t smem_addr, const void* gptr) {
    asm volatile("cp.async.cg.shared.global [%0], [%1], 16;"
                 :: "r"(smem_addr), "l"(gptr));
}
#define CP_COMMIT() asm volatile("cp.async.commit_group;" ::: "memory")
#define CP_WAIT0()  asm volatile("cp.async.wait_group 0;" ::: "memory")

// ---- GEMM: logits = img @ cur^T, bf16 out to HBM --------------------------
// 128 CTAs: rb = bid>>1 (128-row block), nh = bid&1 (4096-col half).
__global__ __launch_bounds__(NTH, 1)
void gemm_kernel() {
    extern __shared__ char smraw[];
    const uint32_t smb = (uint32_t)__cvta_generic_to_shared(smraw);
    __nv_bfloat16* As = (__nv_bfloat16*)(smraw + SM_A);

    const int tid  = threadIdx.x;
    const int lane = tid & 31;
    const int wid  = tid >> 5;
    const int mW   = wid & 7;
    const int nG   = wid >> 3;
    const int rb   = blockIdx.x >> 1;
    const int nh   = blockIdx.x & 1;
    const int rowBase  = rb * BM;
    const int colBase0 = nh * 4096;
    const __nv_bfloat16* Asrc = g_bf;
    const __nv_bfloat16* Bsrc = g_bf + NROWS * DIM;

    // persistent A rows (128 x 256)
    {
        const uint4* src = (const uint4*)(Asrc + (size_t)rowBase * DIM);
        #pragma unroll
        for (int i = 0; i < 8; ++i) {
            int idx = tid + i * NTH;
            int r = idx >> 5, c = idx & 31;
            *(uint4*)&As[r * STR + c * 8] = src[r * 32 + c];
        }
    }
    // prefetch B panel 0
    {
        const char* src = (const char*)(Bsrc + (size_t)colBase0 * DIM);
        #pragma unroll
        for (int i = 0; i < 4; ++i) {
            int idx = tid + i * NTH;
            int r = idx >> 5, c = idx & 31;
            cp_async16(smb + SM_B0 + (uint32_t)(r * STR + c * 8) * 2u, src + idx * 16);
        }
        CP_COMMIT();
    }

    const int aRow     = mW * 16 + (lane & 8) + (lane & 7);
    const int aColHalf = (lane & 16) ? 8 : 0;
    const int bRowOff  = ((lane & 16) ? 8 : 0) + (lane & 7);
    const int bColHalf = (lane & 8) ? 8 : 0;
    const uint32_t smA = smb + SM_A;

    const int mrow0 = mW * 16 + (lane >> 2);
    const int nSub  = (lane & 3) * 2;

    float acc[4][4];
    #pragma unroll
    for (int nt = 0; nt < 4; ++nt)
        #pragma unroll
        for (int q = 0; q < 4; ++q) acc[nt][q] = 0.0f;

    #pragma unroll 1
    for (int p = 0; p < 64; ++p) {
        CP_WAIT0();
        __syncthreads();   // panel p visible; prior panel's LDSMs done -> other buf free
        if (p + 1 < 64) {
            const char* src = (const char*)(Bsrc + (size_t)(colBase0 + (p + 1) * BN) * DIM);
            const uint32_t dst = smb + (((p + 1) & 1) ? SM_B1 : SM_B0);
            #pragma unroll
            for (int i = 0; i < 4; ++i) {
                int idx = tid + i * NTH;
                int r = idx >> 5, c = idx & 31;
                cp_async16(dst + (uint32_t)(r * STR + c * 8) * 2u, src + idx * 16);
            }
            CP_COMMIT();
        }
        const uint32_t smB = smb + ((p & 1) ? SM_B1 : SM_B0);

        #pragma unroll 1
        for (int ks = 0; ks < DIM / 16; ++ks) {
            uint32_t a0, a1, a2, a3;
            ldsm4(a0, a1, a2, a3,
                  smA + (uint32_t)(aRow * STR + ks * 16 + aColHalf) * 2u);
            #pragma unroll
            for (int ntp = 0; ntp < 2; ++ntp) {
                uint32_t b0, b1, b2, b3;
                ldsm4(b0, b1, b2, b3,
                      smB + (uint32_t)((nG * 32 + ntp * 16 + bRowOff) * STR + ks * 16 + bColHalf) * 2u);
                mma16816(acc[2 * ntp],     a0, a1, a2, a3, b0, b1);
                mma16816(acc[2 * ntp + 1], a0, a1, a2, a3, b2, b3);
            }
        }

        // store bf16 logits (row0 & row0+8, 4 n-tiles x 2 cols)
        {
            const int colBase = colBase0 + p * BN + nG * 32;
            const int row0 = rowBase + mrow0;
            #pragma unroll
            for (int nt = 0; nt < 4; ++nt) {
                int col = colBase + nt * 8 + nSub;
                *(__nv_bfloat162*)(g_logits + (size_t)row0 * NROWS + col) =
                    __floats2bfloat162_rn(acc[nt][0], acc[nt][1]);
                *(__nv_bfloat162*)(g_logits + (size_t)(row0 + 8) * NROWS + col) =
                    __floats2bfloat162_rn(acc[nt][2], acc[nt][3]);
                acc[nt][0] = acc[nt][1] = acc[nt][2] = acc[nt][3] = 0.0f;
            }
        }
    }
}

// ---- top-k + loss: 128 CTAs (dir = bid>>6, blk = bid&63) ------------------
#define TK_NTH 256
#define TSTR   130                         // bf16 elems per tile row (65 words)
#define TSM_TILE 0                         // 128 x 130 bf16 = 33280 B
#define TSM_TK   33280                     // 128 x 33 f32
#define TSM_RL   (TSM_TK + 128*33*4)       // 128 f32
#define TSM_TOT  (TSM_RL + 512)

__global__ __launch_bounds__(TK_NTH, 1)
void topk_kernel() {
    extern __shared__ char smraw[];
    __nv_bfloat16* tile = (__nv_bfloat16*)(smraw + TSM_TILE);
    uint32_t* tileU = (uint32_t*)tile;
    float* TkAll = (float*)(smraw + TSM_TK);
    float* Rl    = (float*)(smraw + TSM_RL);

    const int tid = threadIdx.x;
    const int dir = blockIdx.x >> 6;       // 0: rows of L, 1: cols of L
    const int blk = blockIdx.x & 63;

    for (int i = tid; i < 128 * 33; i += TK_NTH) TkAll[i] = -INFINITY;
    __syncthreads();

    float* tk = TkAll + tid * 33;          // valid for tid<128
    float thr = -INFINITY;
    float pos = 0.0f;

    if (dir == 0) {
        // ---- row scan, direct from gmem with 8-wide hmax filter ----
        if (tid < 128) {
            const int o = blk * 128 + tid;                 // global row
            const uint4* rowp = (const uint4*)(g_logits + (size_t)o * NROWS);
            const int qIdx = o >> 3;                       // uint4 holding diag
            const int qOff = o & 7;
            #pragma unroll 4
            for (int i = 0; i < NROWS / 8; ++i) {
                uint4 v = rowp[i];
                __nv_bfloat162 p0 = *(__nv_bfloat162*)&v.x;
                __nv_bfloat162 p1 = *(__nv_bfloat162*)&v.y;
                __nv_bfloat162 p2 = *(__nv_bfloat162*)&v.z;
                __nv_bfloat162 p3 = *(__nv_bfloat162*)&v.w;
                __nv_bfloat162 m01 = __hmax2(p0, p1);
                __nv_bfloat162 m23 = __hmax2(p2, p3);
                __nv_bfloat162 m   = __hmax2(m01, m23);
                float mf = fmaxf(__low2float(m), __high2float(m));
                if (mf > thr || i == qIdx) {
                    float vals[8];
                    vals[0] = __low2float(p0); vals[1] = __high2float(p0);
                    vals[2] = __low2float(p1); vals[3] = __high2float(p1);
                    vals[4] = __low2float(p2); vals[5] = __high2float(p2);
                    vals[6] = __low2float(p3); vals[7] = __high2float(p3);
                    if (i == qIdx) { pos = vals[qOff]; vals[qOff] = -INFINITY; }
                    #pragma unroll
                    for (int q = 0; q < 8; ++q) {
                        float val = vals[q];
                        if (val > thr) {
                            int ip = 31;
                            while (ip > 0 && tk[ip - 1] < val) { tk[ip] = tk[ip - 1]; --ip; }
                            tk[ip] = val;
                            thr = tk[31];
                        }
                    }
                }
            }
        }
    } else {
        // ---- column scan via SMEM tile transpose ----
        const int cBase = blk * 128;
        #pragma unroll 1
        for (int ch = 0; ch < 64; ++ch) {
            // load 128x128 bf16 tile: rows ch*128.., cols cBase..
            {
                const uint4* src = (const uint4*)(g_logits + (size_t)(ch * 128) * NROWS + cBase);
                #pragma unroll
                for (int i = 0; i < 8; ++i) {
                    int idx = tid + i * TK_NTH;           // 2048 uint4
                    int r = idx >> 4, c16 = idx & 15;
                    uint4 v = src[(size_t)r * (NROWS / 8) + c16];
                    uint32_t* d = &tileU[r * 65 + c16 * 4];
                    d[0] = v.x; d[1] = v.y; d[2] = v.z; d[3] = v.w;
                }
            }
            __syncthreads();
            if (tid < 128) {
                const bool dchunk = (ch == blk);
                if (dchunk) pos = __bfloat162float(tile[tid * TSTR + tid]);
                #pragma unroll 4
                for (int r = 0; r < 128; ++r) {
                    if (dchunk && r == tid) continue;
                    float val = __bfloat162float(tile[r * TSTR + tid]);
                    if (val > thr) {
                        int ip = 31;
                        while (ip > 0 && tk[ip - 1] < val) { tk[ip] = tk[ip - 1]; --ip; }
                        tk[ip] = val;
                        thr = tk[31];
                    }
                }
            }
            __syncthreads();
        }
    }

    // ---- per-object loss ----
    if (tid < 128) {
        const float invT = 1.0f / 0.07f;
        float pp = pos * invT;
        float m = fmaxf(pp, tk[0] * invT);
        float s = expf(pp - m);
        #pragma unroll
        for (int i = 0; i < 32; ++i) s += expf(tk[i] * invT - m);
        Rl[tid] = m + logf(s) - pp;
    }
    __syncthreads();
    if (tid == 0) {
        float sum = 0.0f;
        for (int r = 0; r < 128; ++r) sum += Rl[r];   // fixed order: deterministic
        g_partial[blockIdx.x] = sum;
    }
}

__global__ void finalize_kernel(float* out) {
    if (threadIdx.x == 0) {
        float sum = 0.0f;
        for (int i = 0; i < 128; ++i) sum += g_partial[i];
        out[0] = sum * (0.5f / (float)NROWS);
    }
}

extern "C" void kernel_launch(void* const* d_in, const int* in_sizes, int n_in,
                              void* d_out, int out_size) {
    const float* img = (const float*)d_in[0];
    const float* cur = (const float*)d_in[1];
    float* out = (float*)d_out;

    const int cthreads = 2 * NROWS * DIM / 4;
    convert_kernel<<<(cthreads + 255) / 256, 256>>>(img, cur);

    cudaFuncSetAttribute(gemm_kernel, cudaFuncAttributeMaxDynamicSharedMemorySize, SM_GEMM);
    gemm_kernel<<<128, NTH, SM_GEMM>>>();

    cudaFuncSetAttribute(topk_kernel, cudaFuncAttributeMaxDynamicSharedMemorySize, TSM_TOT);
    topk_kernel<<<128, TK_NTH, TSM_TOT>>>();

    finalize_kernel<<<1, 1>>>(out);
}

// round 9
// speedup vs baseline: 3.0664x; 3.0664x over previous
#include <cuda_runtime.h>
#include <cuda_fp16.h>
#include <math.h>
#include <stdint.h>

// ---------------------------------------------------------------------------
// HardNegativeContrastiveLoss N=8192 D=256. Round 7: revert to fused r5
// structure (no logit materialization — r6 showed scattered stores kill it),
// switch bf16/f32-accum -> fp16/f16-accum mma.sync (2x rate on legacy path),
// packed-half epilogue filter. 512 thr, cp.async double-buffered B panels.
// ---------------------------------------------------------------------------

#define NROWS 8192
#define DIM   256
#define BM    128
#define BN    64
#define NTH   512
#define NPANEL (NROWS / BN)     // 128
#define STR   264               // fp16 elems per SMEM row (528 B, LDSM conflict-free)

// ---- SMEM byte offsets ----
#define SM_TK    0                        // 128 x 33 f32 sorted desc top-32
#define SM_CNT   16896                    // 128 u32 candidate counts
#define SM_PS    17408                    // 128 f32 positives
#define SM_RL    17920                    // 128 f32 row losses
#define SM_CAND  18432                    // 128 x 69 f32 candidates
#define SM_A     53760                    // 128 x 264 fp16  (67584 B)
#define SM_B0    121344                   // 64 x 264 fp16   (33792 B)
#define SM_B1    155136
#define SM_TOTAL 188928

__device__ __half g_hf[2 * NROWS * DIM];
__device__ float g_partial[128];

// ---- fp32 -> fp16 conversion ----------------------------------------------
__global__ void convert_kernel(const float* __restrict__ a, const float* __restrict__ b) {
    int i = blockIdx.x * blockDim.x + threadIdx.x;
    const int n = NROWS * DIM / 4;
    if (i < n) {
        float4 v = ((const float4*)a)[i];
        __half2* o = (__half2*)(g_hf) + i * 2;
        o[0] = __floats2half2_rn(v.x, v.y);
        o[1] = __floats2half2_rn(v.z, v.w);
    } else if (i < 2 * n) {
        int j = i - n;
        float4 v = ((const float4*)b)[j];
        __half2* o = (__half2*)(g_hf + NROWS * DIM) + j * 2;
        o[0] = __floats2half2_rn(v.x, v.y);
        o[1] = __floats2half2_rn(v.z, v.w);
    }
}

// ---- PTX helpers ----------------------------------------------------------
__device__ __forceinline__ void ldsm4(uint32_t& r0, uint32_t& r1, uint32_t& r2, uint32_t& r3,
                                      uint32_t addr) {
    asm volatile("ldmatrix.sync.aligned.m8n8.x4.shared.b16 {%0,%1,%2,%3}, [%4];"
                 : "=r"(r0), "=r"(r1), "=r"(r2), "=r"(r3) : "r"(addr));
}
// f16 x f16 -> f16 accumulate, D/C packed half2 x2
__device__ __forceinline__ void mma16816h(uint32_t& c0, uint32_t& c1,
                                          uint32_t a0, uint32_t a1, uint32_t a2, uint32_t a3,
                                          uint32_t b0, uint32_t b1) {
    asm volatile("mma.sync.aligned.m16n8k16.row.col.f16.f16.f16.f16 "
                 "{%0,%1}, {%2,%3,%4,%5}, {%6,%7}, {%0,%1};"
                 : "+r"(c0), "+r"(c1)
                 : "r"(a0), "r"(a1), "r"(a2), "r"(a3), "r"(b0), "r"(b1));
}
__device__ __forceinline__ void cp_async16(uint32_t smem_addr, const void* gptr) {
    asm volatile("cp.async.cg.shared.global [%0], [%1], 16;"
                 :: "r"(smem_addr), "l"(gptr));
}
#define CP_COMMIT() asm volatile("cp.async.commit_group;" ::: "memory")
#define CP_WAIT(N)  asm volatile("cp.async.wait_group " #N ";" ::: "memory")

__device__ __forceinline__ __half2 h2(uint32_t v) { return *(__half2*)&v; }

// ---- fused GEMM + top-32 + loss -------------------------------------------
__global__ __launch_bounds__(NTH, 1)
void pass_kernel() {
    extern __shared__ char smraw[];
    const uint32_t smb = (uint32_t)__cvta_generic_to_shared(smraw);
    float* Tk     = (float*)(smraw + SM_TK);
    unsigned* Cnt = (unsigned*)(smraw + SM_CNT);
    float* Ps     = (float*)(smraw + SM_PS);
    float* Rl     = (float*)(smraw + SM_RL);
    float* Cand   = (float*)(smraw + SM_CAND);
    __half* As    = (__half*)(smraw + SM_A);

    const int tid  = threadIdx.x;
    const int lane = tid & 31;
    const int wid  = tid >> 5;
    const int mW   = wid & 7;              // m-tile: rows [16*mW, 16*mW+16)
    const int nG   = wid >> 3;             // n-group: cols [32*nG, 32*nG+32) of panel
    const int pass = blockIdx.x >> 6;
    const int rowBlock = blockIdx.x & 63;
    const int rowBase  = rowBlock * BM;
    const __half* Asrc = g_hf + (size_t)pass       * NROWS * DIM;
    const __half* Bsrc = g_hf + (size_t)(1 - pass) * NROWS * DIM;

    // persistent A rows (128 x 256)
    {
        const uint4* src = (const uint4*)(Asrc + (size_t)rowBase * DIM);
        #pragma unroll
        for (int i = 0; i < 8; ++i) {
            int idx = tid + i * NTH;       // 4096 uint4 total
            int r = idx >> 5, c = idx & 31;
            *(uint4*)&As[r * STR + c * 8] = src[r * 32 + c];
        }
    }
    for (int i = tid; i < 128 * 33; i += NTH) Tk[i] = -INFINITY;
    if (tid < 128) Cnt[tid] = 0;

    // prefetch B panel 0 (2048 uint4)
    {
        const char* src = (const char*)(Bsrc);
        #pragma unroll
        for (int i = 0; i < 4; ++i) {
            int idx = tid + i * NTH;
            int r = idx >> 5, c = idx & 31;
            cp_async16(smb + SM_B0 + (uint32_t)(r * STR + c * 8) * 2u, src + idx * 16);
        }
        CP_COMMIT();
    }

    // ldmatrix lane addressing
    const int aRow     = mW * 16 + (lane & 8) + (lane & 7);
    const int aColHalf = (lane & 16) ? 8 : 0;
    const int bRowOff  = ((lane & 16) ? 8 : 0) + (lane & 7);
    const int bColHalf = (lane & 8) ? 8 : 0;
    const uint32_t smA = smb + SM_A;

    const int mrow0 = mW * 16 + (lane >> 2);   // rows owned by this thread
    const int nSub  = (lane & 3) * 2;
    const int grow0 = rowBase + mrow0;
    const int grow1 = grow0 + 8;
    const int diagP0 = grow0 >> 6;             // panel holding row's diagonal
    const int diagP1 = grow1 >> 6;

    // acc[nt][0]: rows mrow0, cols {nSub, nSub+1} packed; acc[nt][1]: row +8
    uint32_t acc[4][2];
    #pragma unroll
    for (int nt = 0; nt < 4; ++nt) { acc[nt][0] = 0u; acc[nt][1] = 0u; }

    __syncthreads();

    #pragma unroll 1
    for (int p = 0; p < NPANEL; ++p) {
        const int s = p & 1;
        const uint32_t smB = smb + (s ? SM_B1 : SM_B0);

        // prefetch next panel into the other buffer
        if (p + 1 < NPANEL) {
            const char* src = (const char*)(Bsrc + (size_t)(p + 1) * BN * DIM);
            const uint32_t dst = smb + ((p + 1) & 1 ? SM_B1 : SM_B0);
            #pragma unroll
            for (int i = 0; i < 4; ++i) {
                int idx = tid + i * NTH;
                int r = idx >> 5, c = idx & 31;
                cp_async16(dst + (uint32_t)(r * STR + c * 8) * 2u, src + idx * 16);
            }
            CP_COMMIT();
            CP_WAIT(1);
        } else {
            CP_WAIT(0);
        }
        __syncthreads();

        // ---- m16n32 x k256 per warp ----
        #pragma unroll 1
        for (int ks = 0; ks < DIM / 16; ++ks) {
            uint32_t a0, a1, a2, a3;
            ldsm4(a0, a1, a2, a3,
                  smA + (uint32_t)(aRow * STR + ks * 16 + aColHalf) * 2u);
            #pragma unroll
            for (int ntp = 0; ntp < 2; ++ntp) {
                uint32_t b0, b1, b2, b3;
                ldsm4(b0, b1, b2, b3,
                      smB + (uint32_t)((nG * 32 + ntp * 16 + bRowOff) * STR + ks * 16 + bColHalf) * 2u);
                mma16816h(acc[2 * ntp][0],     acc[2 * ntp][1],     a0, a1, a2, a3, b0, b1);
                mma16816h(acc[2 * ntp + 1][0], acc[2 * ntp + 1][1], a0, a1, a2, a3, b2, b3);
            }
        }

        // ---- packed-half register filter + rare push ----
        const int colBase = p * BN + nG * 32;
        {
            float thr = Tk[mrow0 * 33 + 31];
            __half2 m01 = __hmax2(h2(acc[0][0]), h2(acc[1][0]));
            __half2 m23 = __hmax2(h2(acc[2][0]), h2(acc[3][0]));
            __half2 mm  = __hmax2(m01, m23);
            float mx = fmaxf(__low2float(mm), __high2float(mm));
            if (mx > thr || p == diagP0) {
                #pragma unroll
                for (int nt = 0; nt < 4; ++nt) {
                    __half2 hv = h2(acc[nt][0]);
                    float v0 = __low2float(hv), v1 = __high2float(hv);
                    int col = colBase + nt * 8 + nSub;
                    if (p == diagP0 && col == grow0) { Ps[mrow0] = v0; }
                    else if (v0 > thr) {
                        unsigned idx = atomicAdd(&Cnt[mrow0], 1u);
                        Cand[mrow0 * 69 + idx] = v0;
                    }
                    if (p == diagP0 && col + 1 == grow0) { Ps[mrow0] = v1; }
                    else if (v1 > thr) {
                        unsigned idx = atomicAdd(&Cnt[mrow0], 1u);
                        Cand[mrow0 * 69 + idx] = v1;
                    }
                }
            }
            float thr1 = Tk[(mrow0 + 8) * 33 + 31];
            __half2 n01 = __hmax2(h2(acc[0][1]), h2(acc[1][1]));
            __half2 n23 = __hmax2(h2(acc[2][1]), h2(acc[3][1]));
            __half2 nm  = __hmax2(n01, n23);
            float mx1 = fmaxf(__low2float(nm), __high2float(nm));
            if (mx1 > thr1 || p == diagP1) {
                #pragma unroll
                for (int nt = 0; nt < 4; ++nt) {
                    __half2 hv = h2(acc[nt][1]);
                    float v0 = __low2float(hv), v1 = __high2float(hv);
                    int col = colBase + nt * 8 + nSub;
                    if (p == diagP1 && col == grow1) { Ps[mrow0 + 8] = v0; }
                    else if (v0 > thr1) {
                        unsigned idx = atomicAdd(&Cnt[mrow0 + 8], 1u);
                        Cand[(mrow0 + 8) * 69 + idx] = v0;
                    }
                    if (p == diagP1 && col + 1 == grow1) { Ps[mrow0 + 8] = v1; }
                    else if (v1 > thr1) {
                        unsigned idx = atomicAdd(&Cnt[mrow0 + 8], 1u);
                        Cand[(mrow0 + 8) * 69 + idx] = v1;
                    }
                }
            }
        }
        #pragma unroll
        for (int nt = 0; nt < 4; ++nt) { acc[nt][0] = 0u; acc[nt][1] = 0u; }

        __syncthreads();   // pushes visible to merge threads

        // ---- merge candidates into sorted top-32 (thread = row) ----
        if (tid < BM) {
            int c = (int)Cnt[tid];
            if (c > 0) {
                float* tk = Tk + tid * 33;
                float thr = tk[31];
                for (int i = 0; i < c; ++i) {
                    float val = Cand[tid * 69 + i];
                    if (val > thr) {
                        int ip = 31;
                        while (ip > 0 && tk[ip - 1] < val) { tk[ip] = tk[ip - 1]; --ip; }
                        tk[ip] = val;
                        thr = tk[31];
                    }
                }
                Cnt[tid] = 0;
            }
        }
        __syncthreads();   // merged thr + cleared counts visible; B buffer reusable
    }

    // ---- per-row loss ----
    if (tid < BM) {
        const float invT = 1.0f / 0.07f;
        const float* tk = Tk + tid * 33;
        float pp = Ps[tid] * invT;
        float m = fmaxf(pp, tk[0] * invT);
        float s = expf(pp - m);
        #pragma unroll
        for (int i = 0; i < 32; ++i) s += expf(tk[i] * invT - m);
        Rl[tid] = m + logf(s) - pp;
    }
    __syncthreads();
    if (tid == 0) {
        float sum = 0.0f;
        for (int r = 0; r < BM; ++r) sum += Rl[r];   // fixed order: deterministic
        g_partial[blockIdx.x] = sum;
    }
}

__global__ void finalize_kernel(float* out) {
    if (threadIdx.x == 0) {
        float sum = 0.0f;
        for (int i = 0; i < 128; ++i) sum += g_partial[i];
        out[0] = sum * (0.5f / (float)NROWS);
    }
}

extern "C" void kernel_launch(void* const* d_in, const int* in_sizes, int n_in,
                              void* d_out, int out_size) {
    const float* img = (const float*)d_in[0];
    const float* cur = (const float*)d_in[1];
    float* out = (float*)d_out;

    const int cthreads = 2 * NROWS * DIM / 4;
    convert_kernel<<<(cthreads + 255) / 256, 256>>>(img, cur);

    cudaFuncSetAttribute(pass_kernel, cudaFuncAttributeMaxDynamicSharedMemorySize, SM_TOTAL);
    pass_kernel<<<128, NTH, SM_TOTAL>>>();
    finalize_kernel<<<1, 1>>>(out);
}